// round 16
// baseline (speedup 1.0000x reference)
#include <cuda_runtime.h>
#include <cuda_bf16.h>
#include <cstdint>

#define MAXN 100000
#define MAXE 1600000

typedef unsigned long long u64;

// ---------------- device scratch ----------------
__device__ __align__(128) __nv_bfloat16 g_Wcat_h[256 * 256];
__device__ __align__(128) __nv_bfloat16 g_Wcat_l[256 * 256];
__device__ __align__(128) __nv_bfloat16 g_Wm2n_h[256 * 128];
__device__ __align__(128) __nv_bfloat16 g_Wm2n_l[256 * 128];
__device__ __align__(128) float g_bcat[256];
__device__ __align__(128) __nv_bfloat16 g_Wce_bf[128 * 32];
__device__ __align__(128) float g_xl[MAXN * 128];
__device__ __align__(128) float g_xr[MAXN * 128];
__device__ __align__(128) __nv_bfloat16 g_ew[(size_t)MAXE * 128];
__device__ __align__(128) __nv_bfloat16 g_agg_h[MAXN * 128];
__device__ __align__(128) __nv_bfloat16 g_agg_l[MAXN * 128];
__device__ __align__(128) int   g_deg[MAXN];
__device__ __align__(128) int   g_rowptr[MAXN + 1];
__device__ __align__(128) int   g_cursor[MAXN];
__device__ __align__(128) u64   g_se[MAXE];
__device__ int g_is64;

// ---------------- helpers ----------------
__device__ __forceinline__ uint32_t smem_u32(const void* p) {
    uint32_t a;
    asm("{ .reg .u64 t; cvta.to.shared.u64 t, %1; cvt.u32.u64 %0, t; }" : "=r"(a) : "l"(p));
    return a;
}
__device__ __forceinline__ void ldsm4(uint32_t& r0, uint32_t& r1, uint32_t& r2, uint32_t& r3, uint32_t addr) {
    asm volatile("ldmatrix.sync.aligned.m8n8.x4.shared.b16 {%0,%1,%2,%3}, [%4];"
                 : "=r"(r0), "=r"(r1), "=r"(r2), "=r"(r3) : "r"(addr));
}
__device__ __forceinline__ void mma_bf16(float* c, const uint32_t* a, const uint32_t* b) {
    asm volatile(
        "mma.sync.aligned.m16n8k16.row.col.f32.bf16.bf16.f32 "
        "{%0,%1,%2,%3}, {%4,%5,%6,%7}, {%8,%9}, {%0,%1,%2,%3};"
        : "+f"(c[0]), "+f"(c[1]), "+f"(c[2]), "+f"(c[3])
        : "r"(a[0]), "r"(a[1]), "r"(a[2]), "r"(a[3]), "r"(b[0]), "r"(b[1]));
}
__device__ __forceinline__ uint32_t pkbf(__nv_bfloat16 a, __nv_bfloat16 b) {
    return (uint32_t)__bfloat16_as_ushort(a) | ((uint32_t)__bfloat16_as_ushort(b) << 16);
}
__device__ __forceinline__ void cp16(uint32_t dst, const void* src, bool pred) {
    int sz = pred ? 16 : 0;
    asm volatile("cp.async.cg.shared.global [%0], [%1], 16, %2;" :: "r"(dst), "l"(src), "r"(sz));
}
#define CP_COMMIT() asm volatile("cp.async.commit_group;" ::: "memory")
#define CP_WAIT(n)  asm volatile("cp.async.wait_group %0;" :: "n"(n) : "memory")

// ---------------- [0] detect ----------------
__global__ void detect_kernel(const int* __restrict__ ei32) {
    int lane = threadIdx.x & 31;
    int zeros = 0;
#pragma unroll
    for (int i = 0; i < 4; i++) {
        int idx = i * 32 + lane;
        if (ei32[2 * idx + 1] == 0) zeros++;
    }
#pragma unroll
    for (int o = 16; o; o >>= 1) zeros += __shfl_xor_sync(0xffffffffu, zeros, o);
    if (lane == 0 && blockIdx.x == 0) g_is64 = (zeros >= 120) ? 1 : 0;
}
__device__ __forceinline__ int load_idx(const int* ei32, long long pos, int is64) {
    return is64 ? ei32[2 * pos] : ei32[pos];
}
__device__ __forceinline__ int clampi(int v, int lo, int hi) {
    return v < lo ? lo : (v > hi ? hi : v);
}

// ---------------- [1] weight folding + bf16 split ----------------
__global__ void combine_kernel(const float* __restrict__ Wl, const float* __restrict__ Wr,
                               const float* __restrict__ We, const float* __restrict__ Wn2m,
                               const float* __restrict__ Wr2m, const float* __restrict__ bl,
                               const float* __restrict__ br, const float* __restrict__ Wm2n) {
    int i = blockIdx.x * blockDim.x + threadIdx.x;
    if (i < 256 * 256) {
        int o = i >> 8, k = i & 255;
        const float* wrow = (o < 128) ? &Wl[o * 128] : &Wr[(o - 128) * 128];
        float s = 0.f;
#pragma unroll 8
        for (int j = 0; j < 128; j++) s += wrow[j] * Wn2m[j * 256 + k];
        __nv_bfloat16 h = __float2bfloat16(s);
        __nv_bfloat16 l = __float2bfloat16(s - __bfloat162float(h));
        g_Wcat_h[o * 256 + k] = h;
        g_Wcat_l[o * 256 + k] = l;
    } else if (i < 256 * 256 + 128 * 32) {
        int r = i - 256 * 256;
        int o = r >> 5, k = r & 31;
        float s = 0.f;
#pragma unroll 8
        for (int j = 0; j < 128; j++) s += We[o * 128 + j] * Wr2m[j * 32 + k];
        g_Wce_bf[o * 32 + k] = __float2bfloat16(s);
    } else if (i < 256 * 256 + 128 * 32 + 256) {
        int k = i - 256 * 256 - 128 * 32;
        g_bcat[k] = (k < 128) ? bl[k] : br[k - 128];
    } else if (i < 256 * 256 + 128 * 32 + 256 + 256 * 128) {
        int r = i - (256 * 256 + 128 * 32 + 256);
        float s = Wm2n[r];
        __nv_bfloat16 h = __float2bfloat16(s);
        __nv_bfloat16 l = __float2bfloat16(s - __bfloat162float(h));
        g_Wm2n_h[r] = h;
        g_Wm2n_l[r] = l;
    }
}

#define SM_STRIDE 40

// ---------------- eW = rbf @ Wce^T, smem-staged coalesced epilogue ----------------
// dyn smem: A_s[0,10240) B_s[10240,20480) out_s[20480,53248)
#define EW_TILES 4
__global__ __launch_bounds__(256, 2) void gemm_ew(const float* __restrict__ rbf, int E) {
    extern __shared__ __align__(16) char ews[];
    __nv_bfloat16* A_s = (__nv_bfloat16*)ews;
    __nv_bfloat16* B_s = (__nv_bfloat16*)(ews + 10240);
    uint32_t* out_s = (uint32_t*)(ews + 20480);   // [128][64] u32, XOR-swizzled

    int tid = threadIdx.x, lane = tid & 31, wid = tid >> 5;
    int wm = wid & 3, wn = wid >> 2;
    int base_row = blockIdx.x * (128 * EW_TILES);

#pragma unroll
    for (int c = tid; c < 512; c += 256) {
        int row = c >> 2, ko = (c & 3) * 8;
        *(uint4*)&B_s[row * SM_STRIDE + ko] = *(const uint4*)&g_Wce_bf[row * 32 + ko];
    }

    float4 pref[4];
#pragma unroll
    for (int q = 0; q < 4; q++) {
        int c = tid + q * 256;
        int row = c >> 3, kq = (c & 7) * 4;
        int gr = base_row + row;
        pref[q] = (gr < E) ? *(const float4*)&rbf[(size_t)gr * 32 + kq]
                           : make_float4(0.f, 0.f, 0.f, 0.f);
    }

    for (int t = 0; t < EW_TILES; t++) {
        int row0 = base_row + t * 128;
        __syncthreads();
#pragma unroll
        for (int q = 0; q < 4; q++) {
            int c = tid + q * 256;
            int row = c >> 3, kq = (c & 7) * 4;
            float4 v = pref[q];
            *(uint2*)&A_s[row * SM_STRIDE + kq] =
                make_uint2(pkbf(__float2bfloat16(v.x), __float2bfloat16(v.y)),
                           pkbf(__float2bfloat16(v.z), __float2bfloat16(v.w)));
        }
        __syncthreads();

        if (t + 1 < EW_TILES) {
#pragma unroll
            for (int q = 0; q < 4; q++) {
                int c = tid + q * 256;
                int row = c >> 3, kq = (c & 7) * 4;
                int gr = base_row + (t + 1) * 128 + row;
                pref[q] = (gr < E) ? *(const float4*)&rbf[(size_t)gr * 32 + kq]
                                   : make_float4(0.f, 0.f, 0.f, 0.f);
            }
        }

        float acc[2][8][4];
#pragma unroll
        for (int i = 0; i < 2; i++)
#pragma unroll
            for (int j = 0; j < 8; j++)
#pragma unroll
                for (int q = 0; q < 4; q++) acc[i][j][q] = 0.f;

#pragma unroll
        for (int kk = 0; kk < 32; kk += 16) {
            uint32_t ah[2][4];
#pragma unroll
            for (int mt = 0; mt < 2; mt++) {
                int r = wm * 32 + mt * 16 + (lane & 15);
                int kcol = kk + (lane >> 4) * 8;
                ldsm4(ah[mt][0], ah[mt][1], ah[mt][2], ah[mt][3], smem_u32(&A_s[r * SM_STRIDE + kcol]));
            }
#pragma unroll
            for (int np = 0; np < 4; np++) {
                int rn = wn * 64 + np * 16 + (lane & 7) + ((lane >> 4) & 1) * 8;
                int kb = kk + ((lane >> 3) & 1) * 8;
                uint32_t bh[4];
                ldsm4(bh[0], bh[1], bh[2], bh[3], smem_u32(&B_s[rn * SM_STRIDE + kb]));
#pragma unroll
                for (int mt = 0; mt < 2; mt++) {
                    mma_bf16(acc[mt][np * 2 + 0], ah[mt], bh + 0);
                    mma_bf16(acc[mt][np * 2 + 1], ah[mt], bh + 2);
                }
            }
        }

        // stage fragments in out_s (swizzled: u4-group index XOR (row&7))
#pragma unroll
        for (int mt = 0; mt < 2; mt++) {
#pragma unroll
            for (int nt = 0; nt < 8; nt++) {
                int g = wn * 8 + nt;         // uint4-group (8 groups of 4 u32 per row... g in 0..15 halves)
                int l2 = lane & 3;
                int rA = wm * 32 + mt * 16 + (lane >> 2);
                int rB = rA + 8;
                // u32 column index c2 = g*4 + l2 (g in 0..15 -> c2 0..63)
                out_s[rA * 64 + (((g >> 1) ^ (rA & 7)) << 3 | ((g & 1) << 2) | l2)] =
                    pkbf(__float2bfloat16(acc[mt][nt][0]), __float2bfloat16(acc[mt][nt][1]));
                out_s[rB * 64 + (((g >> 1) ^ (rB & 7)) << 3 | ((g & 1) << 2) | l2)] =
                    pkbf(__float2bfloat16(acc[mt][nt][2]), __float2bfloat16(acc[mt][nt][3]));
            }
        }
        __syncthreads();
        // coalesced 32B stores: 2048 uint2-pairs -> use uint4 over 8-u32 swizzle groups
        for (int i = tid; i < 1024; i += 256) {    // 1024 groups of 8 u32 (32B)
            int row = i >> 3;                       // 8 groups per row
            int g8 = i & 7;                         // 8-u32 group index
            int sg = g8 ^ (row & 7);                // unswizzle
            int gr = row0 + row;
            if (gr < E) {
                uint4 v0 = *(uint4*)&out_s[row * 64 + (sg << 3)];
                uint4 v1 = *(uint4*)&out_s[row * 64 + (sg << 3) + 4];
                *(uint4*)&g_ew[(size_t)gr * 128 + g8 * 16] = v0;
                *(uint4*)&g_ew[(size_t)gr * 128 + g8 * 16 + 8] = v1;
            }
        }
    }
}

// ---------------- CSR build ----------------
__global__ void zero_deg_kernel(int n) {
    int i = blockIdx.x * blockDim.x + threadIdx.x;
    if (i < n) g_deg[i] = 0;
}
__global__ void hist_kernel(const int* __restrict__ ei32, int E, int n) {
    int e = blockIdx.x * blockDim.x + threadIdx.x;
    if (e < E) {
        int d = clampi(load_idx(ei32, (long long)E + e, g_is64), 0, n - 1);
        atomicAdd(&g_deg[d], 1);
    }
}
__global__ void scan_kernel(int n) {
    __shared__ int warp_sums[32];
    __shared__ int s_carry;
    int tid = threadIdx.x, lane = tid & 31, wid = tid >> 5;
    if (tid == 0) s_carry = 0;
    __syncthreads();
    for (int base = 0; base < n; base += 1024) {
        int i = base + tid;
        int v = (i < n) ? g_deg[i] : 0;
        int x = v;
#pragma unroll
        for (int o = 1; o < 32; o <<= 1) {
            int t = __shfl_up_sync(0xffffffffu, x, o);
            if (lane >= o) x += t;
        }
        if (lane == 31) warp_sums[wid] = x;
        __syncthreads();
        if (wid == 0) {
            int w = warp_sums[lane];
#pragma unroll
            for (int o = 1; o < 32; o <<= 1) {
                int t = __shfl_up_sync(0xffffffffu, w, o);
                if (lane >= o) w += t;
            }
            warp_sums[lane] = w;
        }
        __syncthreads();
        int carry = s_carry;
        int woff = (wid > 0) ? warp_sums[wid - 1] : 0;
        if (i < n) {
            int excl = carry + woff + x - v;
            g_rowptr[i] = excl;
            g_cursor[i] = excl;
        }
        __syncthreads();
        if (tid == 1023) s_carry = carry + warp_sums[31];
    }
    __syncthreads();
    if (threadIdx.x == 0) g_rowptr[n] = s_carry;
}
__global__ void fill_kernel(const int* __restrict__ ei32, int E, int n) {
    int e = blockIdx.x * blockDim.x + threadIdx.x;
    if (e < E) {
        int is64 = g_is64;
        int d = clampi(load_idx(ei32, (long long)E + e, is64), 0, n - 1);
        int s = clampi(load_idx(ei32, e, is64), 0, n - 1);
        int p = atomicAdd(&g_cursor[d], 1);
        p = clampi(p, 0, E - 1);
        g_se[p] = ((u64)(uint32_t)e << 32) | (uint32_t)s;
    }
}

// ---------------- fused node GEMM ----------------
#define NB_STG 20480

__global__ __launch_bounds__(256, 2) void gemm_node_fused(const float* __restrict__ x, int M) {
    extern __shared__ __align__(16) char dynsmem[];
    uint32_t sbase = smem_u32(dynsmem);
    int tid = threadIdx.x, lane = tid & 31, wid = tid >> 5;
    int wm = wid & 3, wn = wid >> 2;
    int gy = blockIdx.y;
    int row0 = blockIdx.x * 128;
    int bcol0 = gy * 128;
    const __nv_bfloat16* Bh_g = g_Wcat_h;
    const __nv_bfloat16* Bl_g = g_Wcat_l;
    float* C = gy ? g_xr : g_xl;
    const float* bias = g_bcat + bcol0;
    constexpr int K = 256, NK = 8;

    float acc[2][8][4];
#pragma unroll
    for (int i = 0; i < 2; i++)
#pragma unroll
        for (int j = 0; j < 8; j++)
#pragma unroll
            for (int q = 0; q < 4; q++) acc[i][j][q] = 0.f;

    auto loadB = [&](int kc, int st) {
        uint32_t sb = sbase + 20480 + st * NB_STG;
#pragma unroll
        for (int c = tid; c < 512; c += 256) {
            int row = c >> 2, ko = (c & 3) * 8;
            cp16(sb + row * 80 + ko * 2, &Bh_g[(size_t)(bcol0 + row) * K + kc * 32 + ko], true);
            cp16(sb + 10240 + row * 80 + ko * 2, &Bl_g[(size_t)(bcol0 + row) * K + kc * 32 + ko], true);
        }
    };

    float4 pref[4];
#pragma unroll
    for (int q = 0; q < 4; q++) {
        int c = tid + q * 256;
        int row = c >> 3, c4 = (c & 7) * 4;
        int gr = row0 + row;
        pref[q] = (gr < M) ? *(const float4*)&x[(size_t)gr * K + c4]
                           : make_float4(0.f, 0.f, 0.f, 0.f);
    }
    loadB(0, 0);
    CP_COMMIT();

    for (int kc = 0; kc < NK; kc++) {
        int st = kc & 1;
        __syncthreads();
#pragma unroll
        for (int q = 0; q < 4; q++) {
            int c = tid + q * 256;
            int row = c >> 3, kq = (c & 7) * 4;
            float4 v = pref[q];
            __nv_bfloat16 h0 = __float2bfloat16(v.x), h1 = __float2bfloat16(v.y);
            __nv_bfloat16 h2 = __float2bfloat16(v.z), h3 = __float2bfloat16(v.w);
            __nv_bfloat16 l0 = __float2bfloat16(v.x - __bfloat162float(h0));
            __nv_bfloat16 l1 = __float2bfloat16(v.y - __bfloat162float(h1));
            __nv_bfloat16 l2 = __float2bfloat16(v.z - __bfloat162float(h2));
            __nv_bfloat16 l3 = __float2bfloat16(v.w - __bfloat162float(h3));
            *(uint2*)(dynsmem + (size_t)row * 80 + kq * 2) = make_uint2(pkbf(h0, h1), pkbf(h2, h3));
            *(uint2*)(dynsmem + 10240 + (size_t)row * 80 + kq * 2) = make_uint2(pkbf(l0, l1), pkbf(l2, l3));
        }
        if (kc + 1 < NK) {
            loadB(kc + 1, st ^ 1);
            CP_COMMIT();
#pragma unroll
            for (int q = 0; q < 4; q++) {
                int c = tid + q * 256;
                int row = c >> 3, c4 = (c & 7) * 4;
                int gr = row0 + row;
                pref[q] = (gr < M) ? *(const float4*)&x[(size_t)gr * K + (kc + 1) * 32 + c4]
                                   : make_float4(0.f, 0.f, 0.f, 0.f);
            }
            CP_WAIT(1);
        } else {
            CP_WAIT(0);
        }
        __syncthreads();

        uint32_t sa = sbase;
        uint32_t sb = sbase + 20480 + st * NB_STG;
#pragma unroll
        for (int kk = 0; kk < 32; kk += 16) {
            uint32_t ah[2][4], al[2][4];
#pragma unroll
            for (int mt = 0; mt < 2; mt++) {
                int r = wm * 32 + mt * 16 + (lane & 15);
                int kcol = kk + (lane >> 4) * 8;
                ldsm4(ah[mt][0], ah[mt][1], ah[mt][2], ah[mt][3], sa + r * 80 + kcol * 2);
                ldsm4(al[mt][0], al[mt][1], al[mt][2], al[mt][3], sa + 10240 + r * 80 + kcol * 2);
            }
#pragma unroll
            for (int np = 0; np < 4; np++) {
                int rn = wn * 64 + np * 16 + (lane & 7) + ((lane >> 4) & 1) * 8;
                int kb = kk + ((lane >> 3) & 1) * 8;
                uint32_t bh[4], bl[4];
                ldsm4(bh[0], bh[1], bh[2], bh[3], sb + rn * 80 + kb * 2);
                ldsm4(bl[0], bl[1], bl[2], bl[3], sb + 10240 + rn * 80 + kb * 2);
#pragma unroll
                for (int mt = 0; mt < 2; mt++) {
                    mma_bf16(acc[mt][np * 2 + 0], ah[mt], bh + 0);
                    mma_bf16(acc[mt][np * 2 + 1], ah[mt], bh + 2);
                    mma_bf16(acc[mt][np * 2 + 0], al[mt], bh + 0);
                    mma_bf16(acc[mt][np * 2 + 1], al[mt], bh + 2);
                    mma_bf16(acc[mt][np * 2 + 0], ah[mt], bl + 0);
                    mma_bf16(acc[mt][np * 2 + 1], ah[mt], bl + 2);
                }
            }
        }
    }

#pragma unroll
    for (int mt = 0; mt < 2; mt++) {
#pragma unroll
        for (int nt = 0; nt < 8; nt++) {
            int colL = wn * 64 + nt * 8 + (lane & 3) * 2;
            float b0 = bias[colL], b1 = bias[colL + 1];
            int r0 = row0 + wm * 32 + mt * 16 + (lane >> 2);
            if (r0 < M) {
                float2 v = make_float2(acc[mt][nt][0] + b0, acc[mt][nt][1] + b1);
                *(float2*)&C[(size_t)r0 * 128 + colL] = v;
            }
            int r1 = r0 + 8;
            if (r1 < M) {
                float2 v = make_float2(acc[mt][nt][2] + b0, acc[mt][nt][3] + b1);
                *(float2*)&C[(size_t)r1 * 128 + colL] = v;
            }
        }
    }
}

// ---------------- output GEMM (A pre-split) ----------------
#define STG_BYTES 40960
#define OFF_AH 0
#define OFF_AL 10240
#define OFF_BH 20480
#define OFF_BL 30720

__global__ __launch_bounds__(256, 2) void gemm_out_mma(float* __restrict__ out, int M) {
    extern __shared__ __align__(16) char dynsmem[];
    uint32_t sbase = smem_u32(dynsmem);
    int tid = threadIdx.x, lane = tid & 31, wid = tid >> 5;
    int wm = wid & 3, wn = wid >> 2;
    int gy = blockIdx.y;
    int row0 = blockIdx.x * 128;
    int bcol0 = gy * 128;
    constexpr int K = 128, NK = 4;

    float acc[2][8][4];
#pragma unroll
    for (int i = 0; i < 2; i++)
#pragma unroll
        for (int j = 0; j < 8; j++)
#pragma unroll
            for (int q = 0; q < 4; q++) acc[i][j][q] = 0.f;

    auto load_chunk = [&](int kc, int st) {
        uint32_t sb = sbase + st * STG_BYTES;
#pragma unroll
        for (int c = tid; c < 512; c += 256) {
            int row = c >> 2, ko = (c & 3) * 8;
            int gr = row0 + row;
            bool p = gr < M;
            cp16(sb + OFF_AH + row * 80 + ko * 2, &g_agg_h[(size_t)gr * K + kc * 32 + ko], p);
            cp16(sb + OFF_AL + row * 80 + ko * 2, &g_agg_l[(size_t)gr * K + kc * 32 + ko], p);
        }
#pragma unroll
        for (int c = tid; c < 512; c += 256) {
            int row = c >> 2, ko = (c & 3) * 8;
            cp16(sb + OFF_BH + row * 80 + ko * 2, &g_Wm2n_h[(size_t)(bcol0 + row) * K + kc * 32 + ko], true);
            cp16(sb + OFF_BL + row * 80 + ko * 2, &g_Wm2n_l[(size_t)(bcol0 + row) * K + kc * 32 + ko], true);
        }
    };

    load_chunk(0, 0);
    CP_COMMIT();

    for (int kc = 0; kc < NK; kc++) {
        int st = kc & 1;
        if (kc + 1 < NK) {
            load_chunk(kc + 1, (kc + 1) & 1);
            CP_COMMIT();
            CP_WAIT(1);
        } else {
            CP_WAIT(0);
        }
        __syncthreads();

        uint32_t sb = sbase + st * STG_BYTES;
#pragma unroll
        for (int kk = 0; kk < 32; kk += 16) {
            uint32_t ah[2][4], al[2][4];
#pragma unroll
            for (int mt = 0; mt < 2; mt++) {
                int r = wm * 32 + mt * 16 + (lane & 15);
                int kcol = kk + (lane >> 4) * 8;
                ldsm4(ah[mt][0], ah[mt][1], ah[mt][2], ah[mt][3], sb + OFF_AH + r * 80 + kcol * 2);
                ldsm4(al[mt][0], al[mt][1], al[mt][2], al[mt][3], sb + OFF_AL + r * 80 + kcol * 2);
            }
#pragma unroll
            for (int np = 0; np < 4; np++) {
                int rn = wn * 64 + np * 16 + (lane & 7) + ((lane >> 4) & 1) * 8;
                int kb = kk + ((lane >> 3) & 1) * 8;
                uint32_t bh[4], bl[4];
                ldsm4(bh[0], bh[1], bh[2], bh[3], sb + OFF_BH + rn * 80 + kb * 2);
                ldsm4(bl[0], bl[1], bl[2], bl[3], sb + OFF_BL + rn * 80 + kb * 2);
#pragma unroll
                for (int mt = 0; mt < 2; mt++) {
                    mma_bf16(acc[mt][np * 2 + 0], ah[mt], bh + 0);
                    mma_bf16(acc[mt][np * 2 + 1], ah[mt], bh + 2);
                    mma_bf16(acc[mt][np * 2 + 0], al[mt], bh + 0);
                    mma_bf16(acc[mt][np * 2 + 1], al[mt], bh + 2);
                    mma_bf16(acc[mt][np * 2 + 0], ah[mt], bl + 0);
                    mma_bf16(acc[mt][np * 2 + 1], ah[mt], bl + 2);
                }
            }
        }
        __syncthreads();
    }

#pragma unroll
    for (int mt = 0; mt < 2; mt++) {
#pragma unroll
        for (int nt = 0; nt < 8; nt++) {
            int colL = wn * 64 + nt * 8 + (lane & 3) * 2;
            int r0 = row0 + wm * 32 + mt * 16 + (lane >> 2);
            if (r0 < M) {
                float2 v = make_float2(acc[mt][nt][0], acc[mt][nt][1]);
                *(float2*)&out[(size_t)r0 * 256 + bcol0 + colL] = v;
            }
            int r1 = r0 + 8;
            if (r1 < M) {
                float2 v = make_float2(acc[mt][nt][2], acc[mt][nt][3]);
                *(float2*)&out[(size_t)r1 * 256 + bcol0 + colL] = v;
            }
        }
    }
}

// ---------------- fused single-pass edge kernel (8-edge batching) ----------------
__device__ __forceinline__ float lrelu(float v) { return v > 0.f ? v : 0.2f * v; }

__global__ __launch_bounds__(256) void edge_pass_kernel(const float* __restrict__ att,
                                                        const float* __restrict__ bias,
                                                        int n) {
    int tid = threadIdx.x;
    int lane = tid & 31;
    int node = blockIdx.x * 8 + (tid >> 5);
    if (node >= n) return;

    int d0 = lane * 4;
    const float4 xl_own = *(const float4*)&g_xl[node * 128 + d0];
    const float4 xr_own = *(const float4*)&g_xr[node * 128 + d0];
    const float4 att4 = *(const float4*)&att[d0];

    int s = g_rowptr[node];
    int e_end = g_rowptr[node + 1];
    int deg = e_end - s;

    float4 sum_eW = make_float4(0.f, 0.f, 0.f, 0.f);
    float denom = 0.f;
    float4 msg = make_float4(0.f, 0.f, 0.f, 0.f);

    for (int p0 = s; p0 < e_end; p0 += 8) {
        int srcn[8]; float valid[8]; u64 ewp[8];
        float4 xls[8];
#pragma unroll
        for (int j = 0; j < 8; j++) {
            int p = p0 + j;
            int pc = p < e_end ? p : e_end - 1;
            valid[j] = (p < e_end) ? 1.f : 0.f;
            u64 se = g_se[pc];
            srcn[j] = (int)(uint32_t)se;
            int e = (int)(se >> 32);
            ewp[j] = *(const u64*)&g_ew[(size_t)e * 128 + d0];
        }
#pragma unroll
        for (int j = 0; j < 8; j++)
            xls[j] = *(const float4*)&g_xl[srcn[j] * 128 + d0];

#pragma unroll
        for (int j = 0; j < 8; j++) {
            uint32_t lo32, hi32;
            asm("mov.b64 {%0, %1}, %2;" : "=r"(lo32), "=r"(hi32) : "l"(ewp[j]));
            float2 e01 = __bfloat1622float2(*(__nv_bfloat162*)&lo32);
            float2 e23 = __bfloat1622float2(*(__nv_bfloat162*)&hi32);
            float vf = valid[j];
            sum_eW.x += vf * e01.x; sum_eW.y += vf * e01.y;
            sum_eW.z += vf * e23.x; sum_eW.w += vf * e23.y;

            float ux = lrelu(xls[j].x + xr_own.x + e01.x);
            float uy = lrelu(xls[j].y + xr_own.y + e01.y);
            float uz = lrelu(xls[j].z + xr_own.z + e23.x);
            float uw = lrelu(xls[j].w + xr_own.w + e23.y);
            float part = ux * att4.x + uy * att4.y + uz * att4.z + uw * att4.w;
            part += __shfl_xor_sync(0xffffffffu, part, 1);
            part += __shfl_xor_sync(0xffffffffu, part, 2);
            float pe = vf * __expf(part);
            denom += pe;
            msg.x += pe * xls[j].x; msg.y += pe * xls[j].y;
            msg.z += pe * xls[j].z; msg.w += pe * xls[j].w;
        }
    }

    float invdeg = deg > 0 ? 1.0f / (float)deg : 0.0f;
    float lx = lrelu(xl_own.x + xr_own.x + sum_eW.x * invdeg);
    float ly = lrelu(xl_own.y + xr_own.y + sum_eW.y * invdeg);
    float lz = lrelu(xl_own.z + xr_own.z + sum_eW.z * invdeg);
    float lw = lrelu(xl_own.w + xr_own.w + sum_eW.w * invdeg);
    float loop_logit = lx * att4.x + ly * att4.y + lz * att4.z + lw * att4.w;
    loop_logit += __shfl_xor_sync(0xffffffffu, loop_logit, 1);
    loop_logit += __shfl_xor_sync(0xffffffffu, loop_logit, 2);
    float p_loop = __expf(loop_logit);
    denom += p_loop;
    msg.x += p_loop * xl_own.x; msg.y += p_loop * xl_own.y;
    msg.z += p_loop * xl_own.z; msg.w += p_loop * xl_own.w;

    float inv = 1.0f / denom;
    float4 b4 = *(const float4*)&bias[d0];
    float ox = msg.x * inv + b4.x, oy = msg.y * inv + b4.y;
    float oz = msg.z * inv + b4.z, ow = msg.w * inv + b4.w;

    __nv_bfloat16 h0 = __float2bfloat16(ox), h1 = __float2bfloat16(oy);
    __nv_bfloat16 h2 = __float2bfloat16(oz), h3 = __float2bfloat16(ow);
    __nv_bfloat16 l0 = __float2bfloat16(ox - __bfloat162float(h0));
    __nv_bfloat16 l1 = __float2bfloat16(oy - __bfloat162float(h1));
    __nv_bfloat16 l2 = __float2bfloat16(oz - __bfloat162float(h2));
    __nv_bfloat16 l3 = __float2bfloat16(ow - __bfloat162float(h3));
    *(uint2*)&g_agg_h[node * 128 + d0] = make_uint2(pkbf(h0, h1), pkbf(h2, h3));
    *(uint2*)&g_agg_l[node * 128 + d0] = make_uint2(pkbf(l0, l1), pkbf(l2, l3));
}

// ---------------- launch ----------------
extern "C" void kernel_launch(void* const* d_in, const int* in_sizes, int n_in,
                              void* d_out, int out_size) {
    const float* x = (const float*)d_in[0];
    const float* rbf = (const float*)d_in[1];
    const int* ei32 = (const int*)d_in[2];
    const float* Wn2m = (const float*)d_in[4];
    const float* Wr2m = (const float*)d_in[5];
    const float* Wl = (const float*)d_in[6];
    const float* bl = (const float*)d_in[7];
    const float* Wr = (const float*)d_in[8];
    const float* br = (const float*)d_in[9];
    const float* We = (const float*)d_in[10];
    const float* att = (const float*)d_in[11];
    const float* bias = (const float*)d_in[12];
    const float* Wm2n = (const float*)d_in[13];
    float* out = (float*)d_out;

    int N = in_sizes[0] / 256;
    int E = in_sizes[1] / 32;
    if (N > MAXN) N = MAXN;
    if (E > MAXE) E = MAXE;

    static cudaStream_t s1 = 0, s2 = 0, s3 = 0;
    static cudaEvent_t evRoot = 0, ev1 = 0, ev2 = 0, ev3 = 0;
    static bool init_done = false;
    if (!init_done) {
        cudaStreamCreateWithFlags(&s1, cudaStreamNonBlocking);
        cudaStreamCreateWithFlags(&s2, cudaStreamNonBlocking);
        cudaStreamCreateWithFlags(&s3, cudaStreamNonBlocking);
        cudaEventCreateWithFlags(&evRoot, cudaEventDisableTiming);
        cudaEventCreateWithFlags(&ev1, cudaEventDisableTiming);
        cudaEventCreateWithFlags(&ev2, cudaEventDisableTiming);
        cudaEventCreateWithFlags(&ev3, cudaEventDisableTiming);
        cudaFuncSetAttribute(gemm_node_fused, cudaFuncAttributeMaxDynamicSharedMemorySize, 61440);
        cudaFuncSetAttribute(gemm_out_mma, cudaFuncAttributeMaxDynamicSharedMemorySize, 2 * STG_BYTES);
        cudaFuncSetAttribute(gemm_ew, cudaFuncAttributeMaxDynamicSharedMemorySize, 53248);
        init_done = true;
    }

    // idx 0..1: root
    detect_kernel<<<1, 32>>>(ei32);
    int comb_threads = 256 * 256 + 128 * 32 + 256 + 256 * 128;
    combine_kernel<<<(comb_threads + 255) / 256, 256>>>(Wl, Wr, We, Wn2m, Wr2m, bl, br, Wm2n);

    // fork
    cudaEventRecord(evRoot, 0);
    cudaStreamWaitEvent(s1, evRoot, 0);
    cudaStreamWaitEvent(s2, evRoot, 0);
    cudaStreamWaitEvent(s3, evRoot, 0);

    // idx 2: fused node transform (s1)
    gemm_node_fused<<<dim3((N + 127) / 128, 2), 256, 61440, s1>>>(x, N);

    // idx 3: PROFILED SLOT — eW GEMM with coalesced epilogue (s2)
    gemm_ew<<<(E + 128 * EW_TILES - 1) / (128 * EW_TILES), 256, 53248, s2>>>(rbf, E);

    // branch C: CSR build
    zero_deg_kernel<<<(N + 255) / 256, 256, 0, s3>>>(N);
    hist_kernel<<<(E + 255) / 256, 256, 0, s3>>>(ei32, E, N);
    scan_kernel<<<1, 1024, 0, s3>>>(N);
    fill_kernel<<<(E + 255) / 256, 256, 0, s3>>>(ei32, E, N);

    // join
    cudaEventRecord(ev1, s1);
    cudaEventRecord(ev2, s2);
    cudaEventRecord(ev3, s3);
    cudaStreamWaitEvent(0, ev1, 0);
    cudaStreamWaitEvent(0, ev2, 0);
    cudaStreamWaitEvent(0, ev3, 0);

    // tail
    edge_pass_kernel<<<(N + 7) / 8, 256>>>(att, bias, N);
    gemm_out_mma<<<dim3((N + 127) / 128, 2), 256, 2 * STG_BYTES>>>(out, N);
}

// round 17
// speedup vs baseline: 1.2659x; 1.2659x over previous
#include <cuda_runtime.h>
#include <cuda_bf16.h>
#include <cstdint>

#define MAXN 100000
#define MAXE 1600000

typedef unsigned long long u64;

// ---------------- device scratch ----------------
__device__ __align__(128) __nv_bfloat16 g_Wcat_h[256 * 256];
__device__ __align__(128) __nv_bfloat16 g_Wcat_l[256 * 256];
__device__ __align__(128) __nv_bfloat16 g_Wm2n_h[256 * 128];
__device__ __align__(128) __nv_bfloat16 g_Wm2n_l[256 * 128];
__device__ __align__(128) float g_bcat[256];
__device__ __align__(128) __nv_bfloat16 g_Wce_bf[128 * 32];
__device__ __align__(128) float g_xl[MAXN * 128];
__device__ __align__(128) float g_xr[MAXN * 128];
__device__ __align__(128) __nv_bfloat16 g_ew[(size_t)MAXE * 128];
__device__ __align__(128) __nv_bfloat16 g_agg_h[MAXN * 128];
__device__ __align__(128) __nv_bfloat16 g_agg_l[MAXN * 128];
__device__ __align__(128) int   g_deg[MAXN];
__device__ __align__(128) int   g_rowptr[MAXN + 1];
__device__ __align__(128) int   g_cursor[MAXN];
__device__ __align__(128) u64   g_se[MAXE];
__device__ int g_is64;

// ---------------- helpers ----------------
__device__ __forceinline__ uint32_t smem_u32(const void* p) {
    uint32_t a;
    asm("{ .reg .u64 t; cvta.to.shared.u64 t, %1; cvt.u32.u64 %0, t; }" : "=r"(a) : "l"(p));
    return a;
}
__device__ __forceinline__ void ldsm4(uint32_t& r0, uint32_t& r1, uint32_t& r2, uint32_t& r3, uint32_t addr) {
    asm volatile("ldmatrix.sync.aligned.m8n8.x4.shared.b16 {%0,%1,%2,%3}, [%4];"
                 : "=r"(r0), "=r"(r1), "=r"(r2), "=r"(r3) : "r"(addr));
}
__device__ __forceinline__ void mma_bf16(float* c, const uint32_t* a, const uint32_t* b) {
    asm volatile(
        "mma.sync.aligned.m16n8k16.row.col.f32.bf16.bf16.f32 "
        "{%0,%1,%2,%3}, {%4,%5,%6,%7}, {%8,%9}, {%0,%1,%2,%3};"
        : "+f"(c[0]), "+f"(c[1]), "+f"(c[2]), "+f"(c[3])
        : "r"(a[0]), "r"(a[1]), "r"(a[2]), "r"(a[3]), "r"(b[0]), "r"(b[1]));
}
__device__ __forceinline__ uint32_t pkbf(__nv_bfloat16 a, __nv_bfloat16 b) {
    return (uint32_t)__bfloat16_as_ushort(a) | ((uint32_t)__bfloat16_as_ushort(b) << 16);
}
__device__ __forceinline__ void cp16(uint32_t dst, const void* src, bool pred) {
    int sz = pred ? 16 : 0;
    asm volatile("cp.async.cg.shared.global [%0], [%1], 16, %2;" :: "r"(dst), "l"(src), "r"(sz));
}
#define CP_COMMIT() asm volatile("cp.async.commit_group;" ::: "memory")
#define CP_WAIT(n)  asm volatile("cp.async.wait_group %0;" :: "n"(n) : "memory")

// ---------------- [0] detect ----------------
__global__ void detect_kernel(const int* __restrict__ ei32) {
    int lane = threadIdx.x & 31;
    int zeros = 0;
#pragma unroll
    for (int i = 0; i < 4; i++) {
        int idx = i * 32 + lane;
        if (ei32[2 * idx + 1] == 0) zeros++;
    }
#pragma unroll
    for (int o = 16; o; o >>= 1) zeros += __shfl_xor_sync(0xffffffffu, zeros, o);
    if (lane == 0 && blockIdx.x == 0) g_is64 = (zeros >= 120) ? 1 : 0;
}
__device__ __forceinline__ int load_idx(const int* ei32, long long pos, int is64) {
    return is64 ? ei32[2 * pos] : ei32[pos];
}
__device__ __forceinline__ int clampi(int v, int lo, int hi) {
    return v < lo ? lo : (v > hi ? hi : v);
}

// ---------------- [1] weight folding + bf16 split ----------------
__global__ void combine_kernel(const float* __restrict__ Wl, const float* __restrict__ Wr,
                               const float* __restrict__ We, const float* __restrict__ Wn2m,
                               const float* __restrict__ Wr2m, const float* __restrict__ bl,
                               const float* __restrict__ br, const float* __restrict__ Wm2n) {
    int i = blockIdx.x * blockDim.x + threadIdx.x;
    if (i < 256 * 256) {
        int o = i >> 8, k = i & 255;
        const float* wrow = (o < 128) ? &Wl[o * 128] : &Wr[(o - 128) * 128];
        float s = 0.f;
#pragma unroll 8
        for (int j = 0; j < 128; j++) s += wrow[j] * Wn2m[j * 256 + k];
        __nv_bfloat16 h = __float2bfloat16(s);
        __nv_bfloat16 l = __float2bfloat16(s - __bfloat162float(h));
        g_Wcat_h[o * 256 + k] = h;
        g_Wcat_l[o * 256 + k] = l;
    } else if (i < 256 * 256 + 128 * 32) {
        int r = i - 256 * 256;
        int o = r >> 5, k = r & 31;
        float s = 0.f;
#pragma unroll 8
        for (int j = 0; j < 128; j++) s += We[o * 128 + j] * Wr2m[j * 32 + k];
        g_Wce_bf[o * 32 + k] = __float2bfloat16(s);
    } else if (i < 256 * 256 + 128 * 32 + 256) {
        int k = i - 256 * 256 - 128 * 32;
        g_bcat[k] = (k < 128) ? bl[k] : br[k - 128];
    } else if (i < 256 * 256 + 128 * 32 + 256 + 256 * 128) {
        int r = i - (256 * 256 + 128 * 32 + 256);
        float s = Wm2n[r];
        __nv_bfloat16 h = __float2bfloat16(s);
        __nv_bfloat16 l = __float2bfloat16(s - __bfloat162float(h));
        g_Wm2n_h[r] = h;
        g_Wm2n_l[r] = l;
    }
}

#define SM_STRIDE 40

// ---------------- eW = rbf @ Wce^T, smem-staged coalesced epilogue ----------------
// dyn smem: A_s[0,10240) B_s[10240,20480) out_s[20480,53248)
#define EW_TILES 4
__global__ __launch_bounds__(256, 2) void gemm_ew(const float* __restrict__ rbf, int E) {
    extern __shared__ __align__(16) char ews[];
    __nv_bfloat16* A_s = (__nv_bfloat16*)ews;
    __nv_bfloat16* B_s = (__nv_bfloat16*)(ews + 10240);
    uint32_t* out_s = (uint32_t*)(ews + 20480);

    int tid = threadIdx.x, lane = tid & 31, wid = tid >> 5;
    int wm = wid & 3, wn = wid >> 2;
    int base_row = blockIdx.x * (128 * EW_TILES);

#pragma unroll
    for (int c = tid; c < 512; c += 256) {
        int row = c >> 2, ko = (c & 3) * 8;
        *(uint4*)&B_s[row * SM_STRIDE + ko] = *(const uint4*)&g_Wce_bf[row * 32 + ko];
    }

    float4 pref[4];
#pragma unroll
    for (int q = 0; q < 4; q++) {
        int c = tid + q * 256;
        int row = c >> 3, kq = (c & 7) * 4;
        int gr = base_row + row;
        pref[q] = (gr < E) ? *(const float4*)&rbf[(size_t)gr * 32 + kq]
                           : make_float4(0.f, 0.f, 0.f, 0.f);
    }

    for (int t = 0; t < EW_TILES; t++) {
        int row0 = base_row + t * 128;
        __syncthreads();
#pragma unroll
        for (int q = 0; q < 4; q++) {
            int c = tid + q * 256;
            int row = c >> 3, kq = (c & 7) * 4;
            float4 v = pref[q];
            *(uint2*)&A_s[row * SM_STRIDE + kq] =
                make_uint2(pkbf(__float2bfloat16(v.x), __float2bfloat16(v.y)),
                           pkbf(__float2bfloat16(v.z), __float2bfloat16(v.w)));
        }
        __syncthreads();

        if (t + 1 < EW_TILES) {
#pragma unroll
            for (int q = 0; q < 4; q++) {
                int c = tid + q * 256;
                int row = c >> 3, kq = (c & 7) * 4;
                int gr = base_row + (t + 1) * 128 + row;
                pref[q] = (gr < E) ? *(const float4*)&rbf[(size_t)gr * 32 + kq]
                                   : make_float4(0.f, 0.f, 0.f, 0.f);
            }
        }

        float acc[2][8][4];
#pragma unroll
        for (int i = 0; i < 2; i++)
#pragma unroll
            for (int j = 0; j < 8; j++)
#pragma unroll
                for (int q = 0; q < 4; q++) acc[i][j][q] = 0.f;

#pragma unroll
        for (int kk = 0; kk < 32; kk += 16) {
            uint32_t ah[2][4];
#pragma unroll
            for (int mt = 0; mt < 2; mt++) {
                int r = wm * 32 + mt * 16 + (lane & 15);
                int kcol = kk + (lane >> 4) * 8;
                ldsm4(ah[mt][0], ah[mt][1], ah[mt][2], ah[mt][3], smem_u32(&A_s[r * SM_STRIDE + kcol]));
            }
#pragma unroll
            for (int np = 0; np < 4; np++) {
                int rn = wn * 64 + np * 16 + (lane & 7) + ((lane >> 4) & 1) * 8;
                int kb = kk + ((lane >> 3) & 1) * 8;
                uint32_t bh[4];
                ldsm4(bh[0], bh[1], bh[2], bh[3], smem_u32(&B_s[rn * SM_STRIDE + kb]));
#pragma unroll
                for (int mt = 0; mt < 2; mt++) {
                    mma_bf16(acc[mt][np * 2 + 0], ah[mt], bh + 0);
                    mma_bf16(acc[mt][np * 2 + 1], ah[mt], bh + 2);
                }
            }
        }

#pragma unroll
        for (int mt = 0; mt < 2; mt++) {
#pragma unroll
            for (int nt = 0; nt < 8; nt++) {
                int g = wn * 8 + nt;
                int l2 = lane & 3;
                int rA = wm * 32 + mt * 16 + (lane >> 2);
                int rB = rA + 8;
                out_s[rA * 64 + (((g >> 1) ^ (rA & 7)) << 3 | ((g & 1) << 2) | l2)] =
                    pkbf(__float2bfloat16(acc[mt][nt][0]), __float2bfloat16(acc[mt][nt][1]));
                out_s[rB * 64 + (((g >> 1) ^ (rB & 7)) << 3 | ((g & 1) << 2) | l2)] =
                    pkbf(__float2bfloat16(acc[mt][nt][2]), __float2bfloat16(acc[mt][nt][3]));
            }
        }
        __syncthreads();
        for (int i = tid; i < 1024; i += 256) {
            int row = i >> 3;
            int g8 = i & 7;
            int sg = g8 ^ (row & 7);
            int gr = row0 + row;
            if (gr < E) {
                uint4 v0 = *(uint4*)&out_s[row * 64 + (sg << 3)];
                uint4 v1 = *(uint4*)&out_s[row * 64 + (sg << 3) + 4];
                *(uint4*)&g_ew[(size_t)gr * 128 + g8 * 16] = v0;
                *(uint4*)&g_ew[(size_t)gr * 128 + g8 * 16 + 8] = v1;
            }
        }
    }
}

// ---------------- CSR build ----------------
__global__ void zero_deg_kernel(int n) {
    int i = blockIdx.x * blockDim.x + threadIdx.x;
    if (i < n) g_deg[i] = 0;
}
__global__ void hist_kernel(const int* __restrict__ ei32, int E, int n) {
    int e = blockIdx.x * blockDim.x + threadIdx.x;
    if (e < E) {
        int d = clampi(load_idx(ei32, (long long)E + e, g_is64), 0, n - 1);
        atomicAdd(&g_deg[d], 1);
    }
}
__global__ void scan_kernel(int n) {
    __shared__ int warp_sums[32];
    __shared__ int s_carry;
    int tid = threadIdx.x, lane = tid & 31, wid = tid >> 5;
    if (tid == 0) s_carry = 0;
    __syncthreads();
    for (int base = 0; base < n; base += 1024) {
        int i = base + tid;
        int v = (i < n) ? g_deg[i] : 0;
        int x = v;
#pragma unroll
        for (int o = 1; o < 32; o <<= 1) {
            int t = __shfl_up_sync(0xffffffffu, x, o);
            if (lane >= o) x += t;
        }
        if (lane == 31) warp_sums[wid] = x;
        __syncthreads();
        if (wid == 0) {
            int w = warp_sums[lane];
#pragma unroll
            for (int o = 1; o < 32; o <<= 1) {
                int t = __shfl_up_sync(0xffffffffu, w, o);
                if (lane >= o) w += t;
            }
            warp_sums[lane] = w;
        }
        __syncthreads();
        int carry = s_carry;
        int woff = (wid > 0) ? warp_sums[wid - 1] : 0;
        if (i < n) {
            int excl = carry + woff + x - v;
            g_rowptr[i] = excl;
            g_cursor[i] = excl;
        }
        __syncthreads();
        if (tid == 1023) s_carry = carry + warp_sums[31];
    }
    __syncthreads();
    if (threadIdx.x == 0) g_rowptr[n] = s_carry;
}
__global__ void fill_kernel(const int* __restrict__ ei32, int E, int n) {
    int e = blockIdx.x * blockDim.x + threadIdx.x;
    if (e < E) {
        int is64 = g_is64;
        int d = clampi(load_idx(ei32, (long long)E + e, is64), 0, n - 1);
        int s = clampi(load_idx(ei32, e, is64), 0, n - 1);
        int p = atomicAdd(&g_cursor[d], 1);
        p = clampi(p, 0, E - 1);
        g_se[p] = ((u64)(uint32_t)e << 32) | (uint32_t)s;
    }
}

// ---------------- fused node GEMM ----------------
#define NB_STG 20480

__global__ __launch_bounds__(256, 2) void gemm_node_fused(const float* __restrict__ x, int M) {
    extern __shared__ __align__(16) char dynsmem[];
    uint32_t sbase = smem_u32(dynsmem);
    int tid = threadIdx.x, lane = tid & 31, wid = tid >> 5;
    int wm = wid & 3, wn = wid >> 2;
    int gy = blockIdx.y;
    int row0 = blockIdx.x * 128;
    int bcol0 = gy * 128;
    const __nv_bfloat16* Bh_g = g_Wcat_h;
    const __nv_bfloat16* Bl_g = g_Wcat_l;
    float* C = gy ? g_xr : g_xl;
    const float* bias = g_bcat + bcol0;
    constexpr int K = 256, NK = 8;

    float acc[2][8][4];
#pragma unroll
    for (int i = 0; i < 2; i++)
#pragma unroll
        for (int j = 0; j < 8; j++)
#pragma unroll
            for (int q = 0; q < 4; q++) acc[i][j][q] = 0.f;

    auto loadB = [&](int kc, int st) {
        uint32_t sb = sbase + 20480 + st * NB_STG;
#pragma unroll
        for (int c = tid; c < 512; c += 256) {
            int row = c >> 2, ko = (c & 3) * 8;
            cp16(sb + row * 80 + ko * 2, &Bh_g[(size_t)(bcol0 + row) * K + kc * 32 + ko], true);
            cp16(sb + 10240 + row * 80 + ko * 2, &Bl_g[(size_t)(bcol0 + row) * K + kc * 32 + ko], true);
        }
    };

    float4 pref[4];
#pragma unroll
    for (int q = 0; q < 4; q++) {
        int c = tid + q * 256;
        int row = c >> 3, c4 = (c & 7) * 4;
        int gr = row0 + row;
        pref[q] = (gr < M) ? *(const float4*)&x[(size_t)gr * K + c4]
                           : make_float4(0.f, 0.f, 0.f, 0.f);
    }
    loadB(0, 0);
    CP_COMMIT();

    for (int kc = 0; kc < NK; kc++) {
        int st = kc & 1;
        __syncthreads();
#pragma unroll
        for (int q = 0; q < 4; q++) {
            int c = tid + q * 256;
            int row = c >> 3, kq = (c & 7) * 4;
            float4 v = pref[q];
            __nv_bfloat16 h0 = __float2bfloat16(v.x), h1 = __float2bfloat16(v.y);
            __nv_bfloat16 h2 = __float2bfloat16(v.z), h3 = __float2bfloat16(v.w);
            __nv_bfloat16 l0 = __float2bfloat16(v.x - __bfloat162float(h0));
            __nv_bfloat16 l1 = __float2bfloat16(v.y - __bfloat162float(h1));
            __nv_bfloat16 l2 = __float2bfloat16(v.z - __bfloat162float(h2));
            __nv_bfloat16 l3 = __float2bfloat16(v.w - __bfloat162float(h3));
            *(uint2*)(dynsmem + (size_t)row * 80 + kq * 2) = make_uint2(pkbf(h0, h1), pkbf(h2, h3));
            *(uint2*)(dynsmem + 10240 + (size_t)row * 80 + kq * 2) = make_uint2(pkbf(l0, l1), pkbf(l2, l3));
        }
        if (kc + 1 < NK) {
            loadB(kc + 1, st ^ 1);
            CP_COMMIT();
#pragma unroll
            for (int q = 0; q < 4; q++) {
                int c = tid + q * 256;
                int row = c >> 3, c4 = (c & 7) * 4;
                int gr = row0 + row;
                pref[q] = (gr < M) ? *(const float4*)&x[(size_t)gr * K + (kc + 1) * 32 + c4]
                                   : make_float4(0.f, 0.f, 0.f, 0.f);
            }
            CP_WAIT(1);
        } else {
            CP_WAIT(0);
        }
        __syncthreads();

        uint32_t sa = sbase;
        uint32_t sb = sbase + 20480 + st * NB_STG;
#pragma unroll
        for (int kk = 0; kk < 32; kk += 16) {
            uint32_t ah[2][4], al[2][4];
#pragma unroll
            for (int mt = 0; mt < 2; mt++) {
                int r = wm * 32 + mt * 16 + (lane & 15);
                int kcol = kk + (lane >> 4) * 8;
                ldsm4(ah[mt][0], ah[mt][1], ah[mt][2], ah[mt][3], sa + r * 80 + kcol * 2);
                ldsm4(al[mt][0], al[mt][1], al[mt][2], al[mt][3], sa + 10240 + r * 80 + kcol * 2);
            }
#pragma unroll
            for (int np = 0; np < 4; np++) {
                int rn = wn * 64 + np * 16 + (lane & 7) + ((lane >> 4) & 1) * 8;
                int kb = kk + ((lane >> 3) & 1) * 8;
                uint32_t bh[4], bl[4];
                ldsm4(bh[0], bh[1], bh[2], bh[3], sb + rn * 80 + kb * 2);
                ldsm4(bl[0], bl[1], bl[2], bl[3], sb + 10240 + rn * 80 + kb * 2);
#pragma unroll
                for (int mt = 0; mt < 2; mt++) {
                    mma_bf16(acc[mt][np * 2 + 0], ah[mt], bh + 0);
                    mma_bf16(acc[mt][np * 2 + 1], ah[mt], bh + 2);
                    mma_bf16(acc[mt][np * 2 + 0], al[mt], bh + 0);
                    mma_bf16(acc[mt][np * 2 + 1], al[mt], bh + 2);
                    mma_bf16(acc[mt][np * 2 + 0], ah[mt], bl + 0);
                    mma_bf16(acc[mt][np * 2 + 1], ah[mt], bl + 2);
                }
            }
        }
    }

#pragma unroll
    for (int mt = 0; mt < 2; mt++) {
#pragma unroll
        for (int nt = 0; nt < 8; nt++) {
            int colL = wn * 64 + nt * 8 + (lane & 3) * 2;
            float b0 = bias[colL], b1 = bias[colL + 1];
            int r0 = row0 + wm * 32 + mt * 16 + (lane >> 2);
            if (r0 < M) {
                float2 v = make_float2(acc[mt][nt][0] + b0, acc[mt][nt][1] + b1);
                *(float2*)&C[(size_t)r0 * 128 + colL] = v;
            }
            int r1 = r0 + 8;
            if (r1 < M) {
                float2 v = make_float2(acc[mt][nt][2] + b0, acc[mt][nt][3] + b1);
                *(float2*)&C[(size_t)r1 * 128 + colL] = v;
            }
        }
    }
}

// ---------------- output GEMM (A pre-split) ----------------
#define STG_BYTES 40960
#define OFF_AH 0
#define OFF_AL 10240
#define OFF_BH 20480
#define OFF_BL 30720

__global__ __launch_bounds__(256, 2) void gemm_out_mma(float* __restrict__ out, int M) {
    extern __shared__ __align__(16) char dynsmem[];
    uint32_t sbase = smem_u32(dynsmem);
    int tid = threadIdx.x, lane = tid & 31, wid = tid >> 5;
    int wm = wid & 3, wn = wid >> 2;
    int gy = blockIdx.y;
    int row0 = blockIdx.x * 128;
    int bcol0 = gy * 128;
    constexpr int K = 128, NK = 4;

    float acc[2][8][4];
#pragma unroll
    for (int i = 0; i < 2; i++)
#pragma unroll
        for (int j = 0; j < 8; j++)
#pragma unroll
            for (int q = 0; q < 4; q++) acc[i][j][q] = 0.f;

    auto load_chunk = [&](int kc, int st) {
        uint32_t sb = sbase + st * STG_BYTES;
#pragma unroll
        for (int c = tid; c < 512; c += 256) {
            int row = c >> 2, ko = (c & 3) * 8;
            int gr = row0 + row;
            bool p = gr < M;
            cp16(sb + OFF_AH + row * 80 + ko * 2, &g_agg_h[(size_t)gr * K + kc * 32 + ko], p);
            cp16(sb + OFF_AL + row * 80 + ko * 2, &g_agg_l[(size_t)gr * K + kc * 32 + ko], p);
        }
#pragma unroll
        for (int c = tid; c < 512; c += 256) {
            int row = c >> 2, ko = (c & 3) * 8;
            cp16(sb + OFF_BH + row * 80 + ko * 2, &g_Wm2n_h[(size_t)(bcol0 + row) * K + kc * 32 + ko], true);
            cp16(sb + OFF_BL + row * 80 + ko * 2, &g_Wm2n_l[(size_t)(bcol0 + row) * K + kc * 32 + ko], true);
        }
    };

    load_chunk(0, 0);
    CP_COMMIT();

    for (int kc = 0; kc < NK; kc++) {
        int st = kc & 1;
        if (kc + 1 < NK) {
            load_chunk(kc + 1, (kc + 1) & 1);
            CP_COMMIT();
            CP_WAIT(1);
        } else {
            CP_WAIT(0);
        }
        __syncthreads();

        uint32_t sb = sbase + st * STG_BYTES;
#pragma unroll
        for (int kk = 0; kk < 32; kk += 16) {
            uint32_t ah[2][4], al[2][4];
#pragma unroll
            for (int mt = 0; mt < 2; mt++) {
                int r = wm * 32 + mt * 16 + (lane & 15);
                int kcol = kk + (lane >> 4) * 8;
                ldsm4(ah[mt][0], ah[mt][1], ah[mt][2], ah[mt][3], sb + OFF_AH + r * 80 + kcol * 2);
                ldsm4(al[mt][0], al[mt][1], al[mt][2], al[mt][3], sb + OFF_AL + r * 80 + kcol * 2);
            }
#pragma unroll
            for (int np = 0; np < 4; np++) {
                int rn = wn * 64 + np * 16 + (lane & 7) + ((lane >> 4) & 1) * 8;
                int kb = kk + ((lane >> 3) & 1) * 8;
                uint32_t bh[4], bl[4];
                ldsm4(bh[0], bh[1], bh[2], bh[3], sb + OFF_BH + rn * 80 + kb * 2);
                ldsm4(bl[0], bl[1], bl[2], bl[3], sb + OFF_BL + rn * 80 + kb * 2);
#pragma unroll
                for (int mt = 0; mt < 2; mt++) {
                    mma_bf16(acc[mt][np * 2 + 0], ah[mt], bh + 0);
                    mma_bf16(acc[mt][np * 2 + 1], ah[mt], bh + 2);
                    mma_bf16(acc[mt][np * 2 + 0], al[mt], bh + 0);
                    mma_bf16(acc[mt][np * 2 + 1], al[mt], bh + 2);
                    mma_bf16(acc[mt][np * 2 + 0], ah[mt], bl + 0);
                    mma_bf16(acc[mt][np * 2 + 1], ah[mt], bl + 2);
                }
            }
        }
        __syncthreads();
    }

#pragma unroll
    for (int mt = 0; mt < 2; mt++) {
#pragma unroll
        for (int nt = 0; nt < 8; nt++) {
            int colL = wn * 64 + nt * 8 + (lane & 3) * 2;
            int r0 = row0 + wm * 32 + mt * 16 + (lane >> 2);
            if (r0 < M) {
                float2 v = make_float2(acc[mt][nt][0], acc[mt][nt][1]);
                *(float2*)&out[(size_t)r0 * 256 + bcol0 + colL] = v;
            }
            int r1 = r0 + 8;
            if (r1 < M) {
                float2 v = make_float2(acc[mt][nt][2], acc[mt][nt][3]);
                *(float2*)&out[(size_t)r1 * 256 + bcol0 + colL] = v;
            }
        }
    }
}

// ---------------- fused single-pass edge kernel (4-edge batching — reg-safe) ----------------
__device__ __forceinline__ float lrelu(float v) { return v > 0.f ? v : 0.2f * v; }

__global__ __launch_bounds__(256) void edge_pass_kernel(const float* __restrict__ att,
                                                        const float* __restrict__ bias,
                                                        int n) {
    int tid = threadIdx.x;
    int lane = tid & 31;
    int node = blockIdx.x * 8 + (tid >> 5);
    if (node >= n) return;

    int d0 = lane * 4;
    const float4 xl_own = *(const float4*)&g_xl[node * 128 + d0];
    const float4 xr_own = *(const float4*)&g_xr[node * 128 + d0];
    const float4 att4 = *(const float4*)&att[d0];

    int s = g_rowptr[node];
    int e_end = g_rowptr[node + 1];
    int deg = e_end - s;

    float4 sum_eW = make_float4(0.f, 0.f, 0.f, 0.f);
    float denom = 0.f;
    float4 msg = make_float4(0.f, 0.f, 0.f, 0.f);

    for (int p0 = s; p0 < e_end; p0 += 4) {
        int srcn[4]; float valid[4]; u64 ewp[4];
        float4 xls[4];
#pragma unroll
        for (int j = 0; j < 4; j++) {
            int p = p0 + j;
            int pc = p < e_end ? p : e_end - 1;
            valid[j] = (p < e_end) ? 1.f : 0.f;
            u64 se = g_se[pc];
            srcn[j] = (int)(uint32_t)se;
            int e = (int)(se >> 32);
            ewp[j] = *(const u64*)&g_ew[(size_t)e * 128 + d0];
        }
#pragma unroll
        for (int j = 0; j < 4; j++)
            xls[j] = *(const float4*)&g_xl[srcn[j] * 128 + d0];

#pragma unroll
        for (int j = 0; j < 4; j++) {
            uint32_t lo32, hi32;
            asm("mov.b64 {%0, %1}, %2;" : "=r"(lo32), "=r"(hi32) : "l"(ewp[j]));
            float2 e01 = __bfloat1622float2(*(__nv_bfloat162*)&lo32);
            float2 e23 = __bfloat1622float2(*(__nv_bfloat162*)&hi32);
            float vf = valid[j];
            sum_eW.x += vf * e01.x; sum_eW.y += vf * e01.y;
            sum_eW.z += vf * e23.x; sum_eW.w += vf * e23.y;

            float ux = lrelu(xls[j].x + xr_own.x + e01.x);
            float uy = lrelu(xls[j].y + xr_own.y + e01.y);
            float uz = lrelu(xls[j].z + xr_own.z + e23.x);
            float uw = lrelu(xls[j].w + xr_own.w + e23.y);
            float part = ux * att4.x + uy * att4.y + uz * att4.z + uw * att4.w;
            part += __shfl_xor_sync(0xffffffffu, part, 1);
            part += __shfl_xor_sync(0xffffffffu, part, 2);
            float pe = vf * __expf(part);
            denom += pe;
            msg.x += pe * xls[j].x; msg.y += pe * xls[j].y;
            msg.z += pe * xls[j].z; msg.w += pe * xls[j].w;
        }
    }

    float invdeg = deg > 0 ? 1.0f / (float)deg : 0.0f;
    float lx = lrelu(xl_own.x + xr_own.x + sum_eW.x * invdeg);
    float ly = lrelu(xl_own.y + xr_own.y + sum_eW.y * invdeg);
    float lz = lrelu(xl_own.z + xr_own.z + sum_eW.z * invdeg);
    float lw = lrelu(xl_own.w + xr_own.w + sum_eW.w * invdeg);
    float loop_logit = lx * att4.x + ly * att4.y + lz * att4.z + lw * att4.w;
    loop_logit += __shfl_xor_sync(0xffffffffu, loop_logit, 1);
    loop_logit += __shfl_xor_sync(0xffffffffu, loop_logit, 2);
    float p_loop = __expf(loop_logit);
    denom += p_loop;
    msg.x += p_loop * xl_own.x; msg.y += p_loop * xl_own.y;
    msg.z += p_loop * xl_own.z; msg.w += p_loop * xl_own.w;

    float inv = 1.0f / denom;
    float4 b4 = *(const float4*)&bias[d0];
    float ox = msg.x * inv + b4.x, oy = msg.y * inv + b4.y;
    float oz = msg.z * inv + b4.z, ow = msg.w * inv + b4.w;

    __nv_bfloat16 h0 = __float2bfloat16(ox), h1 = __float2bfloat16(oy);
    __nv_bfloat16 h2 = __float2bfloat16(oz), h3 = __float2bfloat16(ow);
    __nv_bfloat16 l0 = __float2bfloat16(ox - __bfloat162float(h0));
    __nv_bfloat16 l1 = __float2bfloat16(oy - __bfloat162float(h1));
    __nv_bfloat16 l2 = __float2bfloat16(oz - __bfloat162float(h2));
    __nv_bfloat16 l3 = __float2bfloat16(ow - __bfloat162float(h3));
    *(uint2*)&g_agg_h[node * 128 + d0] = make_uint2(pkbf(h0, h1), pkbf(h2, h3));
    *(uint2*)&g_agg_l[node * 128 + d0] = make_uint2(pkbf(l0, l1), pkbf(l2, l3));
}

// ---------------- launch ----------------
extern "C" void kernel_launch(void* const* d_in, const int* in_sizes, int n_in,
                              void* d_out, int out_size) {
    const float* x = (const float*)d_in[0];
    const float* rbf = (const float*)d_in[1];
    const int* ei32 = (const int*)d_in[2];
    const float* Wn2m = (const float*)d_in[4];
    const float* Wr2m = (const float*)d_in[5];
    const float* Wl = (const float*)d_in[6];
    const float* bl = (const float*)d_in[7];
    const float* Wr = (const float*)d_in[8];
    const float* br = (const float*)d_in[9];
    const float* We = (const float*)d_in[10];
    const float* att = (const float*)d_in[11];
    const float* bias = (const float*)d_in[12];
    const float* Wm2n = (const float*)d_in[13];
    float* out = (float*)d_out;

    int N = in_sizes[0] / 256;
    int E = in_sizes[1] / 32;
    if (N > MAXN) N = MAXN;
    if (E > MAXE) E = MAXE;

    static cudaStream_t s1 = 0, s2 = 0, s3 = 0;
    static cudaEvent_t evRoot = 0, ev1 = 0, ev2 = 0, ev3 = 0;
    static bool init_done = false;
    if (!init_done) {
        cudaStreamCreateWithFlags(&s1, cudaStreamNonBlocking);
        cudaStreamCreateWithFlags(&s2, cudaStreamNonBlocking);
        cudaStreamCreateWithFlags(&s3, cudaStreamNonBlocking);
        cudaEventCreateWithFlags(&evRoot, cudaEventDisableTiming);
        cudaEventCreateWithFlags(&ev1, cudaEventDisableTiming);
        cudaEventCreateWithFlags(&ev2, cudaEventDisableTiming);
        cudaEventCreateWithFlags(&ev3, cudaEventDisableTiming);
        cudaFuncSetAttribute(gemm_node_fused, cudaFuncAttributeMaxDynamicSharedMemorySize, 61440);
        cudaFuncSetAttribute(gemm_out_mma, cudaFuncAttributeMaxDynamicSharedMemorySize, 2 * STG_BYTES);
        cudaFuncSetAttribute(gemm_ew, cudaFuncAttributeMaxDynamicSharedMemorySize, 53248);
        init_done = true;
    }

    // idx 0..1: root
    detect_kernel<<<1, 32>>>(ei32);
    int comb_threads = 256 * 256 + 128 * 32 + 256 + 256 * 128;
    combine_kernel<<<(comb_threads + 255) / 256, 256>>>(Wl, Wr, We, Wn2m, Wr2m, bl, br, Wm2n);

    // fork
    cudaEventRecord(evRoot, 0);
    cudaStreamWaitEvent(s1, evRoot, 0);
    cudaStreamWaitEvent(s2, evRoot, 0);
    cudaStreamWaitEvent(s3, evRoot, 0);

    // idx 2: fused node transform (s1)
    gemm_node_fused<<<dim3((N + 127) / 128, 2), 256, 61440, s1>>>(x, N);

    // idx 3: PROFILED SLOT — eW GEMM (s2)
    gemm_ew<<<(E + 128 * EW_TILES - 1) / (128 * EW_TILES), 256, 53248, s2>>>(rbf, E);

    // branch C: CSR build
    zero_deg_kernel<<<(N + 255) / 256, 256, 0, s3>>>(N);
    hist_kernel<<<(E + 255) / 256, 256, 0, s3>>>(ei32, E, N);
    scan_kernel<<<1, 1024, 0, s3>>>(N);
    fill_kernel<<<(E + 255) / 256, 256, 0, s3>>>(ei32, E, N);

    // join
    cudaEventRecord(ev1, s1);
    cudaEventRecord(ev2, s2);
    cudaEventRecord(ev3, s3);
    cudaStreamWaitEvent(0, ev1, 0);
    cudaStreamWaitEvent(0, ev2, 0);
    cudaStreamWaitEvent(0, ev3, 0);

    // tail
    edge_pass_kernel<<<(N + 7) / 8, 256>>>(att, bias, N);
    gemm_out_mma<<<dim3((N + 127) / 128, 2), 256, 2 * STG_BYTES>>>(out, N);
}